// round 1
// baseline (speedup 1.0000x reference)
#include <cuda_runtime.h>
#include <cuda_bf16.h>
#include <math_constants.h>

// Problem constants
#define BATCH 2
#define SEQ   2048
#define EMB   1024
#define NH    16
#define HD    64
#define TOK   (BATCH * SEQ)         // 4096
#define QKVF  (3 * EMB)             // 3072
#define ATTN_ELEMS ((size_t)BATCH * NH * SEQ * SEQ)   // 134217728
#define OUT_ELEMS  ((size_t)TOK * EMB)                // 4194304

// Scratch (no cudaMalloc allowed)
__device__ float g_qkv[(size_t)TOK * QKVF];   // 50 MB
__device__ float g_ao [(size_t)TOK * EMB];    // 16 MB

// ---------------------------------------------------------------------------
// Generic C = A[M,K] * W[N,K]^T + bias, row-major, 128x128 tile, BK=8.
// M,N multiples of 128; K multiple of 8.
// ---------------------------------------------------------------------------
__global__ void __launch_bounds__(256) sgemm_tn_bias(
    const float* __restrict__ A, const float* __restrict__ W,
    const float* __restrict__ bias, float* __restrict__ C,
    int M, int N, int K)
{
    __shared__ float As[8][128];
    __shared__ float Ws[8][128];
    const int tid = threadIdx.x;
    const int bm = blockIdx.y * 128;
    const int bn = blockIdx.x * 128;
    const int lrow = tid >> 1;
    const int lcol = (tid & 1) << 2;
    const int ty = tid >> 4;
    const int tx = tid & 15;

    float acc[8][8];
#pragma unroll
    for (int i = 0; i < 8; i++)
#pragma unroll
        for (int j = 0; j < 8; j++) acc[i][j] = 0.f;

    const float* Ap = A + (size_t)(bm + lrow) * K + lcol;
    const float* Wp = W + (size_t)(bn + lrow) * K + lcol;

    for (int k0 = 0; k0 < K; k0 += 8) {
        float4 a4 = *(const float4*)(Ap + k0);
        float4 w4 = *(const float4*)(Wp + k0);
        As[lcol + 0][lrow] = a4.x; As[lcol + 1][lrow] = a4.y;
        As[lcol + 2][lrow] = a4.z; As[lcol + 3][lrow] = a4.w;
        Ws[lcol + 0][lrow] = w4.x; Ws[lcol + 1][lrow] = w4.y;
        Ws[lcol + 2][lrow] = w4.z; Ws[lcol + 3][lrow] = w4.w;
        __syncthreads();
#pragma unroll
        for (int kk = 0; kk < 8; kk++) {
            float am[8], wn[8];
#pragma unroll
            for (int i = 0; i < 8; i++) am[i] = As[kk][ty * 8 + i];
#pragma unroll
            for (int j = 0; j < 8; j++) wn[j] = Ws[kk][tx * 8 + j];
#pragma unroll
            for (int i = 0; i < 8; i++)
#pragma unroll
                for (int j = 0; j < 8; j++) acc[i][j] += am[i] * wn[j];
        }
        __syncthreads();
    }

#pragma unroll
    for (int i = 0; i < 8; i++) {
        int row = bm + ty * 8 + i;
#pragma unroll
        for (int j = 0; j < 8; j += 4) {
            int col = bn + tx * 8 + j;
            float4 o;
            o.x = acc[i][j + 0] + bias[col + 0];
            o.y = acc[i][j + 1] + bias[col + 1];
            o.z = acc[i][j + 2] + bias[col + 2];
            o.w = acc[i][j + 3] + bias[col + 3];
            *(float4*)(C + (size_t)row * N + col) = o;
        }
    }
}

// ---------------------------------------------------------------------------
// Scores: for z = b*16+h, attn[z][s][t] = 0.125 * sum_d Q[s,d]*K[t,d]
// Q,K strided inside g_qkv (row stride QKVF). 128x128 tile, K=64.
// ---------------------------------------------------------------------------
__global__ void __launch_bounds__(256) scores_kernel(
    const float* __restrict__ qkv, float* __restrict__ attn)
{
    const int z = blockIdx.z;
    const int b = z >> 4, h = z & 15;
    const float* Qb = qkv + (size_t)b * SEQ * QKVF + h * HD;
    const float* Kb = Qb + EMB;
    float* Cb = attn + (size_t)z * SEQ * SEQ;

    __shared__ float As[8][128];
    __shared__ float Bs[8][128];
    const int tid = threadIdx.x;
    const int bm = blockIdx.y * 128;
    const int bn = blockIdx.x * 128;
    const int lrow = tid >> 1;
    const int lcol = (tid & 1) << 2;
    const int ty = tid >> 4;
    const int tx = tid & 15;

    float acc[8][8];
#pragma unroll
    for (int i = 0; i < 8; i++)
#pragma unroll
        for (int j = 0; j < 8; j++) acc[i][j] = 0.f;

    const float* Ap = Qb + (size_t)(bm + lrow) * QKVF + lcol;
    const float* Bp = Kb + (size_t)(bn + lrow) * QKVF + lcol;

    for (int k0 = 0; k0 < HD; k0 += 8) {
        float4 a4 = *(const float4*)(Ap + k0);
        float4 b4 = *(const float4*)(Bp + k0);
        As[lcol + 0][lrow] = a4.x; As[lcol + 1][lrow] = a4.y;
        As[lcol + 2][lrow] = a4.z; As[lcol + 3][lrow] = a4.w;
        Bs[lcol + 0][lrow] = b4.x; Bs[lcol + 1][lrow] = b4.y;
        Bs[lcol + 2][lrow] = b4.z; Bs[lcol + 3][lrow] = b4.w;
        __syncthreads();
#pragma unroll
        for (int kk = 0; kk < 8; kk++) {
            float am[8], bn_[8];
#pragma unroll
            for (int i = 0; i < 8; i++) am[i] = As[kk][ty * 8 + i];
#pragma unroll
            for (int j = 0; j < 8; j++) bn_[j] = Bs[kk][tx * 8 + j];
#pragma unroll
            for (int i = 0; i < 8; i++)
#pragma unroll
                for (int j = 0; j < 8; j++) acc[i][j] += am[i] * bn_[j];
        }
        __syncthreads();
    }

    const float scale = 0.125f;  // 1/sqrt(64)
#pragma unroll
    for (int i = 0; i < 8; i++) {
        int row = bm + ty * 8 + i;
#pragma unroll
        for (int j = 0; j < 8; j += 4) {
            int col = bn + tx * 8 + j;
            float4 o;
            o.x = acc[i][j + 0] * scale;
            o.y = acc[i][j + 1] * scale;
            o.z = acc[i][j + 2] * scale;
            o.w = acc[i][j + 3] * scale;
            *(float4*)(Cb + (size_t)row * SEQ + col) = o;
        }
    }
}

// ---------------------------------------------------------------------------
// Row softmax in place: 65536 rows of length 2048, one block/row.
// ---------------------------------------------------------------------------
__global__ void __launch_bounds__(256) softmax_kernel(float* __restrict__ attn)
{
    __shared__ float sh[8];
    float* p = attn + (size_t)blockIdx.x * SEQ;
    const int t = threadIdx.x;
    const int lane = t & 31, warp = t >> 5;

    float v[8];
    float m = -CUDART_INF_F;
#pragma unroll
    for (int i = 0; i < 8; i++) {
        v[i] = p[t + i * 256];
        m = fmaxf(m, v[i]);
    }
#pragma unroll
    for (int o = 16; o > 0; o >>= 1) m = fmaxf(m, __shfl_xor_sync(0xffffffffu, m, o));
    if (lane == 0) sh[warp] = m;
    __syncthreads();
    if (warp == 0) {
        float mm = sh[lane & 7];
#pragma unroll
        for (int o = 4; o > 0; o >>= 1) mm = fmaxf(mm, __shfl_xor_sync(0xffffffffu, mm, o));
        if (lane == 0) sh[0] = mm;
    }
    __syncthreads();
    const float mx = sh[0];
    __syncthreads();

    float s = 0.f;
#pragma unroll
    for (int i = 0; i < 8; i++) {
        v[i] = __expf(v[i] - mx);
        s += v[i];
    }
#pragma unroll
    for (int o = 16; o > 0; o >>= 1) s += __shfl_xor_sync(0xffffffffu, s, o);
    if (lane == 0) sh[warp] = s;
    __syncthreads();
    if (warp == 0) {
        float ss = sh[lane & 7];
#pragma unroll
        for (int o = 4; o > 0; o >>= 1) ss += __shfl_xor_sync(0xffffffffu, ss, o);
        if (lane == 0) sh[0] = ss;
    }
    __syncthreads();
    const float inv = 1.0f / sh[0];

#pragma unroll
    for (int i = 0; i < 8; i++) p[t + i * 256] = v[i] * inv;
}

// ---------------------------------------------------------------------------
// AV: O[s, h*64+d] = sum_t P[z][s][t] * V[t,d]   (per z = b*16+h)
// BM=128, BN=64, BK=16. grid (1, 16, 32).
// ---------------------------------------------------------------------------
__global__ void __launch_bounds__(256) av_kernel(
    const float* __restrict__ attn, const float* __restrict__ qkv,
    float* __restrict__ out)
{
    const int z = blockIdx.z;
    const int b = z >> 4, h = z & 15;
    const float* P = attn + (size_t)z * SEQ * SEQ;
    const float* V = qkv + (size_t)b * SEQ * QKVF + 2 * EMB + h * HD;
    float* O = out + (size_t)b * SEQ * EMB + h * HD;

    __shared__ float As[16][128];
    __shared__ float Bs[16][64];
    const int tid = threadIdx.x;
    const int bm = blockIdx.y * 128;
    const int arow = tid >> 1, acol = (tid & 1) << 3;
    const int brow = tid >> 4, bcol = (tid & 15) << 2;
    const int ty = tid >> 4, tx = tid & 15;

    float acc[8][4];
#pragma unroll
    for (int i = 0; i < 8; i++)
#pragma unroll
        for (int j = 0; j < 4; j++) acc[i][j] = 0.f;

    for (int k0 = 0; k0 < SEQ; k0 += 16) {
        const float* ap = P + (size_t)(bm + arow) * SEQ + k0 + acol;
        float4 a0 = *(const float4*)(ap);
        float4 a1 = *(const float4*)(ap + 4);
        As[acol + 0][arow] = a0.x; As[acol + 1][arow] = a0.y;
        As[acol + 2][arow] = a0.z; As[acol + 3][arow] = a0.w;
        As[acol + 4][arow] = a1.x; As[acol + 5][arow] = a1.y;
        As[acol + 6][arow] = a1.z; As[acol + 7][arow] = a1.w;
        float4 b4 = *(const float4*)(V + (size_t)(k0 + brow) * QKVF + bcol);
        Bs[brow][bcol + 0] = b4.x; Bs[brow][bcol + 1] = b4.y;
        Bs[brow][bcol + 2] = b4.z; Bs[brow][bcol + 3] = b4.w;
        __syncthreads();
#pragma unroll
        for (int kk = 0; kk < 16; kk++) {
            float am[8], bn_[4];
#pragma unroll
            for (int i = 0; i < 8; i++) am[i] = As[kk][ty * 8 + i];
#pragma unroll
            for (int j = 0; j < 4; j++) bn_[j] = Bs[kk][tx * 4 + j];
#pragma unroll
            for (int i = 0; i < 8; i++)
#pragma unroll
                for (int j = 0; j < 4; j++) acc[i][j] += am[i] * bn_[j];
        }
        __syncthreads();
    }

#pragma unroll
    for (int i = 0; i < 8; i++) {
        int row = bm + ty * 8 + i;
        float4 o;
        o.x = acc[i][0]; o.y = acc[i][1]; o.z = acc[i][2]; o.w = acc[i][3];
        *(float4*)(O + (size_t)row * EMB + tx * 4) = o;
    }
}

// ---------------------------------------------------------------------------
extern "C" void kernel_launch(void* const* d_in, const int* in_sizes, int n_in,
                              void* d_out, int out_size)
{
    const float* x     = (const float*)d_in[0];
    const float* qkv_w = (const float*)d_in[1];
    const float* qkv_b = (const float*)d_in[2];
    const float* out_w = (const float*)d_in[3];
    const float* out_b = (const float*)d_in[4];

    float* out_proj = (float*)d_out;                 // [2,2048,1024]
    float* attn     = (float*)d_out + OUT_ELEMS;     // [2,16,2048,2048]

    float* qkv = nullptr;
    float* ao  = nullptr;
    cudaGetSymbolAddress((void**)&qkv, g_qkv);
    cudaGetSymbolAddress((void**)&ao,  g_ao);

    // 1. QKV projection: [4096,3072]
    {
        dim3 grid(QKVF / 128, TOK / 128);
        sgemm_tn_bias<<<grid, 256>>>(x, qkv_w, qkv_b, qkv, TOK, QKVF, EMB);
    }
    // 2. Scores -> attn (raw, scaled)
    {
        dim3 grid(SEQ / 128, SEQ / 128, BATCH * NH);
        scores_kernel<<<grid, 256>>>(qkv, attn);
    }
    // 3. Softmax in place
    {
        softmax_kernel<<<BATCH * NH * SEQ, 256>>>(attn);
    }
    // 4. AV -> g_ao [4096,1024]
    {
        dim3 grid(1, SEQ / 128, BATCH * NH);
        av_kernel<<<grid, 256>>>(attn, qkv, ao);
    }
    // 5. Output projection -> d_out[0 : 4.19M]
    {
        dim3 grid(EMB / 128, TOK / 128);
        sgemm_tn_bias<<<grid, 256>>>(ao, out_w, out_b, out_proj, TOK, EMB, EMB);
    }
}

// round 3
// speedup vs baseline: 1.6636x; 1.6636x over previous
#include <cuda_runtime.h>
#include <cuda_bf16.h>
#include <stdint.h>
#include <math_constants.h>

#define BATCH 2
#define SEQ   2048
#define EMB   1024
#define NH    16
#define HD    64
#define TOK   4096
#define QKVF  3072
#define OUT_ELEMS ((size_t)TOK * EMB)

__device__ float g_qkv[(size_t)TOK * QKVF];   // 50 MB scratch
__device__ float g_ao [(size_t)TOK * EMB];    // 16 MB scratch

// ---------------------------------------------------------------------------
// helpers
// ---------------------------------------------------------------------------
__device__ __forceinline__ void mma_bf16(float* c, const uint32_t* a, uint32_t b0, uint32_t b1) {
    asm volatile(
        "mma.sync.aligned.m16n8k16.row.col.f32.bf16.bf16.f32 "
        "{%0,%1,%2,%3}, {%4,%5,%6,%7}, {%8,%9}, {%0,%1,%2,%3};"
        : "+f"(c[0]), "+f"(c[1]), "+f"(c[2]), "+f"(c[3])
        : "r"(a[0]), "r"(a[1]), "r"(a[2]), "r"(a[3]), "r"(b0), "r"(b1));
}

__device__ __forceinline__ void split2(float x, float y, uint32_t& hi, uint32_t& lo) {
    __nv_bfloat16 bx = __float2bfloat16_rn(x), by = __float2bfloat16_rn(y);
    float rx = x - __bfloat162float(bx);
    float ry = y - __bfloat162float(by);
    __nv_bfloat162 h; h.x = bx; h.y = by;
    __nv_bfloat162 l = __floats2bfloat162_rn(rx, ry);
    hi = *reinterpret_cast<uint32_t*>(&h);
    lo = *reinterpret_cast<uint32_t*>(&l);
}

#define STRB 72   // bytes per smem row (32 bf16 + pad), conflict-free & 8B aligned

// ---------------------------------------------------------------------------
// C[M,N] = A[M,K] @ W[N,K]^T + bias.  Block 128x128, BK=32, 256 thr (8 warps 2x4).
// ---------------------------------------------------------------------------
__global__ void __launch_bounds__(256) mma_gemm_bias(
    const float* __restrict__ A, const float* __restrict__ W,
    const float* __restrict__ bias, float* __restrict__ C, int N, int K)
{
    __shared__ __align__(16) char sAh[128 * STRB];
    __shared__ __align__(16) char sAl[128 * STRB];
    __shared__ __align__(16) char sBh[128 * STRB];
    __shared__ __align__(16) char sBl[128 * STRB];

    const int tid = threadIdx.x;
    const int lane = tid & 31, wid = tid >> 5;
    const int warp_m = wid >> 2, warp_n = wid & 3;     // 2 x 4
    const int bm = blockIdx.y * 128, bn = blockIdx.x * 128;

    const int row = tid >> 1, kq = (tid & 1) * 16;

    float acc[4][4][4];
#pragma unroll
    for (int i = 0; i < 4; i++)
#pragma unroll
        for (int j = 0; j < 4; j++)
#pragma unroll
            for (int l = 0; l < 4; l++) acc[i][j][l] = 0.f;

    const int r4 = lane >> 2, c4 = (lane & 3);

    for (int kt = 0; kt < (K >> 5); kt++) {
        const float* Ap = A + (size_t)(bm + row) * K + kt * 32 + kq;
        const float* Wp = W + (size_t)(bn + row) * K + kt * 32 + kq;
        float4 av[4], wv[4];
#pragma unroll
        for (int i = 0; i < 4; i++) av[i] = *(const float4*)(Ap + i * 4);
#pragma unroll
        for (int i = 0; i < 4; i++) wv[i] = *(const float4*)(Wp + i * 4);
        __syncthreads();
#pragma unroll
        for (int i = 0; i < 4; i++) {
            uint32_t h0, l0, h1, l1;
            split2(av[i].x, av[i].y, h0, l0);
            split2(av[i].z, av[i].w, h1, l1);
            uint32_t off = row * STRB + (kq + i * 4) * 2;
            *(uint2*)(sAh + off) = make_uint2(h0, h1);
            *(uint2*)(sAl + off) = make_uint2(l0, l1);
            split2(wv[i].x, wv[i].y, h0, l0);
            split2(wv[i].z, wv[i].w, h1, l1);
            *(uint2*)(sBh + off) = make_uint2(h0, h1);
            *(uint2*)(sBl + off) = make_uint2(l0, l1);
        }
        __syncthreads();

#pragma unroll
        for (int s = 0; s < 2; s++) {
            const int kb = s * 32;  // byte offset of k16 step
            uint32_t Ah[4][4], Al[4][4];
#pragma unroll
            for (int fm = 0; fm < 4; fm++) {
                uint32_t base = (warp_m * 64 + fm * 16 + r4) * STRB + kb + c4 * 4;
                Ah[fm][0] = *(const uint32_t*)(sAh + base);
                Ah[fm][1] = *(const uint32_t*)(sAh + base + 8 * STRB);
                Ah[fm][2] = *(const uint32_t*)(sAh + base + 16);
                Ah[fm][3] = *(const uint32_t*)(sAh + base + 8 * STRB + 16);
                Al[fm][0] = *(const uint32_t*)(sAl + base);
                Al[fm][1] = *(const uint32_t*)(sAl + base + 8 * STRB);
                Al[fm][2] = *(const uint32_t*)(sAl + base + 16);
                Al[fm][3] = *(const uint32_t*)(sAl + base + 8 * STRB + 16);
            }
#pragma unroll
            for (int fn = 0; fn < 4; fn++) {
                uint32_t bb = (warp_n * 32 + fn * 8 + r4) * STRB + kb + c4 * 4;
                uint32_t Bh0 = *(const uint32_t*)(sBh + bb);
                uint32_t Bh1 = *(const uint32_t*)(sBh + bb + 16);
                uint32_t Bl0 = *(const uint32_t*)(sBl + bb);
                uint32_t Bl1 = *(const uint32_t*)(sBl + bb + 16);
#pragma unroll
                for (int fm = 0; fm < 4; fm++) {
                    mma_bf16(acc[fm][fn], Ah[fm], Bh0, Bh1);
                    mma_bf16(acc[fm][fn], Ah[fm], Bl0, Bl1);
                    mma_bf16(acc[fm][fn], Al[fm], Bh0, Bh1);
                }
            }
        }
    }

    const int cq = (lane & 3) * 2;
#pragma unroll
    for (int fm = 0; fm < 4; fm++) {
#pragma unroll
        for (int fn = 0; fn < 4; fn++) {
            int row0 = bm + warp_m * 64 + fm * 16 + r4;
            int col  = bn + warp_n * 32 + fn * 8 + cq;
            float b0 = bias[col], b1 = bias[col + 1];
            *(float2*)(C + (size_t)row0 * N + col) =
                make_float2(acc[fm][fn][0] + b0, acc[fm][fn][1] + b1);
            *(float2*)(C + (size_t)(row0 + 8) * N + col) =
                make_float2(acc[fm][fn][2] + b0, acc[fm][fn][3] + b1);
        }
    }
}

// ---------------------------------------------------------------------------
// Scores: attn[z][q][t] = 0.125 * sum_d Q[q,d] K[t,d].  K-dim 64 (2 ktiles).
// ---------------------------------------------------------------------------
__global__ void __launch_bounds__(256) mma_scores(
    const float* __restrict__ qkv, float* __restrict__ attn)
{
    __shared__ __align__(16) char sAh[128 * STRB];
    __shared__ __align__(16) char sAl[128 * STRB];
    __shared__ __align__(16) char sBh[128 * STRB];
    __shared__ __align__(16) char sBl[128 * STRB];

    const int tid = threadIdx.x;
    const int lane = tid & 31, wid = tid >> 5;
    const int warp_m = wid >> 2, warp_n = wid & 3;
    const int z = blockIdx.z, b = z >> 4, h = z & 15;
    const int bm = blockIdx.y * 128, bn = blockIdx.x * 128;
    const float* Qb = qkv + (size_t)b * SEQ * QKVF + h * HD;
    const float* Kb = Qb + EMB;
    float* Cb = attn + (size_t)z * SEQ * SEQ;

    const int row = tid >> 1, kq = (tid & 1) * 16;
    const int r4 = lane >> 2, c4 = (lane & 3);

    float acc[4][4][4];
#pragma unroll
    for (int i = 0; i < 4; i++)
#pragma unroll
        for (int j = 0; j < 4; j++)
#pragma unroll
            for (int l = 0; l < 4; l++) acc[i][j][l] = 0.f;

    for (int kt = 0; kt < 2; kt++) {
        const float* Ap = Qb + (size_t)(bm + row) * QKVF + kt * 32 + kq;
        const float* Bp = Kb + (size_t)(bn + row) * QKVF + kt * 32 + kq;
        float4 av[4], wv[4];
#pragma unroll
        for (int i = 0; i < 4; i++) av[i] = *(const float4*)(Ap + i * 4);
#pragma unroll
        for (int i = 0; i < 4; i++) wv[i] = *(const float4*)(Bp + i * 4);
        __syncthreads();
#pragma unroll
        for (int i = 0; i < 4; i++) {
            uint32_t h0, l0, h1, l1;
            split2(av[i].x, av[i].y, h0, l0);
            split2(av[i].z, av[i].w, h1, l1);
            uint32_t off = row * STRB + (kq + i * 4) * 2;
            *(uint2*)(sAh + off) = make_uint2(h0, h1);
            *(uint2*)(sAl + off) = make_uint2(l0, l1);
            split2(wv[i].x, wv[i].y, h0, l0);
            split2(wv[i].z, wv[i].w, h1, l1);
            *(uint2*)(sBh + off) = make_uint2(h0, h1);
            *(uint2*)(sBl + off) = make_uint2(l0, l1);
        }
        __syncthreads();

#pragma unroll
        for (int s = 0; s < 2; s++) {
            const int kb = s * 32;
            uint32_t Ah[4][4], Al[4][4];
#pragma unroll
            for (int fm = 0; fm < 4; fm++) {
                uint32_t base = (warp_m * 64 + fm * 16 + r4) * STRB + kb + c4 * 4;
                Ah[fm][0] = *(const uint32_t*)(sAh + base);
                Ah[fm][1] = *(const uint32_t*)(sAh + base + 8 * STRB);
                Ah[fm][2] = *(const uint32_t*)(sAh + base + 16);
                Ah[fm][3] = *(const uint32_t*)(sAh + base + 8 * STRB + 16);
                Al[fm][0] = *(const uint32_t*)(sAl + base);
                Al[fm][1] = *(const uint32_t*)(sAl + base + 8 * STRB);
                Al[fm][2] = *(const uint32_t*)(sAl + base + 16);
                Al[fm][3] = *(const uint32_t*)(sAl + base + 8 * STRB + 16);
            }
#pragma unroll
            for (int fn = 0; fn < 4; fn++) {
                uint32_t bb = (warp_n * 32 + fn * 8 + r4) * STRB + kb + c4 * 4;
                uint32_t Bh0 = *(const uint32_t*)(sBh + bb);
                uint32_t Bh1 = *(const uint32_t*)(sBh + bb + 16);
                uint32_t Bl0 = *(const uint32_t*)(sBl + bb);
                uint32_t Bl1 = *(const uint32_t*)(sBl + bb + 16);
#pragma unroll
                for (int fm = 0; fm < 4; fm++) {
                    mma_bf16(acc[fm][fn], Ah[fm], Bh0, Bh1);
                    mma_bf16(acc[fm][fn], Ah[fm], Bl0, Bl1);
                    mma_bf16(acc[fm][fn], Al[fm], Bh0, Bh1);
                }
            }
        }
    }

    const int cq = (lane & 3) * 2;
#pragma unroll
    for (int fm = 0; fm < 4; fm++) {
#pragma unroll
        for (int fn = 0; fn < 4; fn++) {
            int row0 = bm + warp_m * 64 + fm * 16 + r4;
            int col  = bn + warp_n * 32 + fn * 8 + cq;
            *(float2*)(Cb + (size_t)row0 * SEQ + col) =
                make_float2(acc[fm][fn][0] * 0.125f, acc[fm][fn][1] * 0.125f);
            *(float2*)(Cb + (size_t)(row0 + 8) * SEQ + col) =
                make_float2(acc[fm][fn][2] * 0.125f, acc[fm][fn][3] * 0.125f);
        }
    }
}

// ---------------------------------------------------------------------------
// AV: O[s, h*64+d] = sum_t P[z][s][t] V[t,d].  Block 128(M)x64(N), BK=32.
// 8 warps as 4(M)x2(N): warp tile 32x32 -> fm=2, fn=4.
// ---------------------------------------------------------------------------
__global__ void __launch_bounds__(256) mma_av(
    const float* __restrict__ attn, const float* __restrict__ qkv,
    float* __restrict__ out)
{
    __shared__ __align__(16) char sAh[128 * STRB];
    __shared__ __align__(16) char sAl[128 * STRB];
    __shared__ __align__(16) char sBh[64 * STRB];
    __shared__ __align__(16) char sBl[64 * STRB];

    const int tid = threadIdx.x;
    const int lane = tid & 31, wid = tid >> 5;
    const int warp_m = wid >> 1, warp_n = wid & 1;    // 4 x 2
    const int z = blockIdx.y, b = z >> 4, h = z & 15;
    const int bm = blockIdx.x * 128;
    const float* P = attn + (size_t)z * SEQ * SEQ;
    const float* V = qkv + (size_t)b * SEQ * QKVF + 2 * EMB + h * HD;
    float* O = out + (size_t)b * SEQ * EMB + h * HD;

    const int row = tid >> 1, kq = (tid & 1) * 16;
    const int vt = tid >> 3, vd = (tid & 7) * 8;      // V loader mapping
    const int r4 = lane >> 2, c4 = (lane & 3);

    float acc[2][4][4];
#pragma unroll
    for (int i = 0; i < 2; i++)
#pragma unroll
        for (int j = 0; j < 4; j++)
#pragma unroll
            for (int l = 0; l < 4; l++) acc[i][j][l] = 0.f;

    for (int kt = 0; kt < (SEQ >> 5); kt++) {
        const float* Ap = P + (size_t)(bm + row) * SEQ + kt * 32 + kq;
        float4 av[4];
#pragma unroll
        for (int i = 0; i < 4; i++) av[i] = *(const float4*)(Ap + i * 4);
        float4 vv[2];
        const float* Vp = V + (size_t)(kt * 32 + vt) * QKVF + vd;
        vv[0] = *(const float4*)(Vp);
        vv[1] = *(const float4*)(Vp + 4);
        __syncthreads();
#pragma unroll
        for (int i = 0; i < 4; i++) {
            uint32_t h0, l0, h1, l1;
            split2(av[i].x, av[i].y, h0, l0);
            split2(av[i].z, av[i].w, h1, l1);
            uint32_t off = row * STRB + (kq + i * 4) * 2;
            *(uint2*)(sAh + off) = make_uint2(h0, h1);
            *(uint2*)(sAl + off) = make_uint2(l0, l1);
        }
        // V transposed into B tile: Bs[d][t]
#pragma unroll
        for (int i = 0; i < 2; i++) {
            float vals[4] = {vv[i].x, vv[i].y, vv[i].z, vv[i].w};
#pragma unroll
            for (int j = 0; j < 4; j++) {
                int d = vd + i * 4 + j;
                __nv_bfloat16 bh = __float2bfloat16_rn(vals[j]);
                float rl = vals[j] - __bfloat162float(bh);
                *(__nv_bfloat16*)(sBh + d * STRB + vt * 2) = bh;
                *(__nv_bfloat16*)(sBl + d * STRB + vt * 2) = __float2bfloat16_rn(rl);
            }
        }
        __syncthreads();

#pragma unroll
        for (int s = 0; s < 2; s++) {
            const int kb = s * 32;
            uint32_t Ah[2][4], Al[2][4];
#pragma unroll
            for (int fm = 0; fm < 2; fm++) {
                uint32_t base = (warp_m * 32 + fm * 16 + r4) * STRB + kb + c4 * 4;
                Ah[fm][0] = *(const uint32_t*)(sAh + base);
                Ah[fm][1] = *(const uint32_t*)(sAh + base + 8 * STRB);
                Ah[fm][2] = *(const uint32_t*)(sAh + base + 16);
                Ah[fm][3] = *(const uint32_t*)(sAh + base + 8 * STRB + 16);
                Al[fm][0] = *(const uint32_t*)(sAl + base);
                Al[fm][1] = *(const uint32_t*)(sAl + base + 8 * STRB);
                Al[fm][2] = *(const uint32_t*)(sAl + base + 16);
                Al[fm][3] = *(const uint32_t*)(sAl + base + 8 * STRB + 16);
            }
#pragma unroll
            for (int fn = 0; fn < 4; fn++) {
                uint32_t bb = (warp_n * 32 + fn * 8 + r4) * STRB + kb + c4 * 4;
                uint32_t Bh0 = *(const uint32_t*)(sBh + bb);
                uint32_t Bh1 = *(const uint32_t*)(sBh + bb + 16);
                uint32_t Bl0 = *(const uint32_t*)(sBl + bb);
                uint32_t Bl1 = *(const uint32_t*)(sBl + bb + 16);
#pragma unroll
                for (int fm = 0; fm < 2; fm++) {
                    mma_bf16(acc[fm][fn], Ah[fm], Bh0, Bh1);
                    mma_bf16(acc[fm][fn], Ah[fm], Bl0, Bl1);
                    mma_bf16(acc[fm][fn], Al[fm], Bh0, Bh1);
                }
            }
        }
    }

    const int cq = (lane & 3) * 2;
#pragma unroll
    for (int fm = 0; fm < 2; fm++) {
#pragma unroll
        for (int fn = 0; fn < 4; fn++) {
            int row0 = bm + warp_m * 32 + fm * 16 + r4;
            int col  = warp_n * 32 + fn * 8 + cq;
            *(float2*)(O + (size_t)row0 * EMB + col) =
                make_float2(acc[fm][fn][0], acc[fm][fn][1]);
            *(float2*)(O + (size_t)(row0 + 8) * EMB + col) =
                make_float2(acc[fm][fn][2], acc[fm][fn][3]);
        }
    }
}

// ---------------------------------------------------------------------------
// Row softmax in place.
// ---------------------------------------------------------------------------
__global__ void __launch_bounds__(256) softmax_kernel(float* __restrict__ attn)
{
    __shared__ float sh[8];
    float* p = attn + (size_t)blockIdx.x * SEQ;
    const int t = threadIdx.x;
    const int lane = t & 31, warp = t >> 5;

    float v[8];
    float m = -CUDART_INF_F;
#pragma unroll
    for (int i = 0; i < 8; i++) {
        v[i] = p[t + i * 256];
        m = fmaxf(m, v[i]);
    }
#pragma unroll
    for (int o = 16; o > 0; o >>= 1) m = fmaxf(m, __shfl_xor_sync(0xffffffffu, m, o));
    if (lane == 0) sh[warp] = m;
    __syncthreads();
    if (warp == 0) {
        float mm = sh[lane & 7];
#pragma unroll
        for (int o = 4; o > 0; o >>= 1) mm = fmaxf(mm, __shfl_xor_sync(0xffffffffu, mm, o));
        if (lane == 0) sh[0] = mm;
    }
    __syncthreads();
    const float mx = sh[0];
    __syncthreads();

    float s = 0.f;
#pragma unroll
    for (int i = 0; i < 8; i++) {
        v[i] = __expf(v[i] - mx);
        s += v[i];
    }
#pragma unroll
    for (int o = 16; o > 0; o >>= 1) s += __shfl_xor_sync(0xffffffffu, s, o);
    if (lane == 0) sh[warp] = s;
    __syncthreads();
    if (warp == 0) {
        float ss = sh[lane & 7];
#pragma unroll
        for (int o = 4; o > 0; o >>= 1) ss += __shfl_xor_sync(0xffffffffu, ss, o);
        if (lane == 0) sh[0] = ss;
    }
    __syncthreads();
    const float inv = 1.0f / sh[0];

#pragma unroll
    for (int i = 0; i < 8; i++) p[t + i * 256] = v[i] * inv;
}

// ---------------------------------------------------------------------------
extern "C" void kernel_launch(void* const* d_in, const int* in_sizes, int n_in,
                              void* d_out, int out_size)
{
    const float* x     = (const float*)d_in[0];
    const float* qkv_w = (const float*)d_in[1];
    const float* qkv_b = (const float*)d_in[2];
    const float* out_w = (const float*)d_in[3];
    const float* out_b = (const float*)d_in[4];

    float* out_proj = (float*)d_out;
    float* attn     = (float*)d_out + OUT_ELEMS;

    float* qkv = nullptr;
    float* ao  = nullptr;
    cudaGetSymbolAddress((void**)&qkv, g_qkv);
    cudaGetSymbolAddress((void**)&ao,  g_ao);

    // 1. QKV projection
    mma_gemm_bias<<<dim3(QKVF / 128, TOK / 128), 256>>>(x, qkv_w, qkv_b, qkv, QKVF, EMB);
    // 2. Scores (scaled)
    mma_scores<<<dim3(SEQ / 128, SEQ / 128, BATCH * NH), 256>>>(qkv, attn);
    // 3. Softmax in place
    softmax_kernel<<<BATCH * NH * SEQ, 256>>>(attn);
    // 4. AV
    mma_av<<<dim3(SEQ / 128, BATCH * NH), 256>>>(attn, qkv, ao);
    // 5. Output projection
    mma_gemm_bias<<<dim3(EMB / 128, TOK / 128), 256>>>(ao, out_w, out_b, out_proj, EMB, EMB);
}